// round 11
// baseline (speedup 1.0000x reference)
#include <cuda_runtime.h>
#include <cstdint>

// 64 steps of diffusion-advection on a 1024x1024 periodic grid -> (T,3,H,W)
// fp32 RGB, ONE persistent kernel.
//
//  - r channel of frame s == u_{s+1} exactly (clipped); frames carry state.
//  - 512 blocks x 512 threads; block owns rows {2b, 2b+1} (thread half =
//    row). Inner row-pair halo goes through parity smem (no L2); only the
//    outer halo row is an L2 read -> global read traffic 4 MB/step.
//  - Each row-half spins only on the single neighbor flag it needs.
//  - Only the r store precedes the flag publish; g/b (2/3 of traffic,
//    never read) stream after it.
//  - launch_bounds(512,4) -> <=32 regs, 4 blocks/SM, 592 slots >= 512:
//    full co-residency (spin-safe).

#define HH 1024
#define WW 1024
#define HW (HH * WW)

#define DT     0.1f
#define ALPHA  0.05f
#define V_X    0.1f
// V_Y == 0 -> du_dy term vanishes.

#define NB 512
#define FS 32                 // flag stride in ints (128 B)

__device__ int g_flags[NB * FS];

__global__ void reset_flags_kernel() {
    const int i = blockIdx.x * blockDim.x + threadIdx.x;   // 0..NB-1
    g_flags[i * FS] = 0;
}

__device__ __forceinline__ int ld_acq(const int* p) {
    int v;
    asm volatile("ld.acquire.gpu.global.b32 %0, [%1];"
                 : "=r"(v) : "l"(p) : "memory");
    return v;
}
__device__ __forceinline__ void st_rel(int* p, int v) {
    asm volatile("st.release.gpu.global.b32 [%0], %1;"
                 :: "l"(p), "r"(v) : "memory");
}

__global__ __launch_bounds__(512, 4)
void physics_persistent_kernel(const float* __restrict__ u_init,
                               float* __restrict__ frames,
                               int n_frames)
{
    __shared__ float4 sInner[2][2][256];   // [parity][rowhalf][c4], 16 KB
    __shared__ float  sEdge[2][2][16];     // [parity][first/last][warp]

    const int tid  = threadIdx.x;
    const int c4   = tid & 255;            // float4 column
    const int half = tid >> 8;             // 0: row 2b, 1: row 2b+1
    const int lane = tid & 31;
    const int wid  = tid >> 5;             // 0..15
    const int wrow = wid & 7;              // warp within the row
    const int b    = blockIdx.x;
    const int y    = 2 * b + half;         // own row

    // Outer halo row: half 0 reads y-1, half 1 reads y+1.
    const int yh   = (half == 0) ? ((y - 1) & (HH - 1))
                                 : ((y + 1) & (HH - 1));
    const int idx  = (y  << 8) + c4;
    const int idxh = (yh << 8) + c4;

    const int nbi = (half == 0) ? ((b - 1) & (NB - 1))
                                : ((b + 1) & (NB - 1));
    const int* flag_nb = &g_flags[nbi * FS];
    int* flag_self = &g_flags[b * FS];

    float4 u = ((const float4*)u_init)[idx];   // u_s for own row
    const float* src = u_init;
    float*       fr  = frames;

    // Seed parity-0 exchange buffers with u_0.
    sInner[0][half][c4] = u;
    if (lane == 0)  sEdge[0][0][wid] = u.x;
    if (lane == 31) sEdge[0][1][wid] = u.w;
    __syncthreads();

    for (int s = 0; s < n_frames; ++s) {
        if (s > 0) {
            while (ld_acq(flag_nb) < s) { }
        }

        // Outer halo (L2 hit: neighbor's r store from step s-1).
        const float4 h = __ldcg(&((const float4*)src)[idxh]);

        const int par = s & 1;
        const float4 inr = sInner[par][half ^ 1][c4];   // inner neighbor row

        const float4 up = (half == 0) ? h : inr;
        const float4 dn = (half == 0) ? inr : h;

        float lw = __shfl_up_sync(0xffffffffu, u.w, 1);
        float rx = __shfl_down_sync(0xffffffffu, u.x, 1);
        if (lane == 0)  lw = sEdge[par][1][(half << 3) | ((wrow + 7) & 7)];
        if (lane == 31) rx = sEdge[par][0][(half << 3) | ((wrow + 1) & 7)];

        const float uc[4] = {u.x,  u.y,  u.z,  u.w};
        const float ul[4] = {lw,   u.x,  u.y,  u.z};
        const float ur[4] = {u.y,  u.z,  u.w,  rx};
        const float uu[4] = {up.x, up.y, up.z, up.w};
        const float ud[4] = {dn.x, dn.y, dn.z, dn.w};

        float4 n;
        float* np = &n.x;
        #pragma unroll
        for (int i = 0; i < 4; ++i) {
            const float lap = ul[i] + ur[i] + uu[i] + ud[i] - 4.0f * uc[i];
            float v = uc[i] + DT * (ALPHA * lap - V_X * (uc[i] - ul[i]));
            np[i] = fminf(fmaxf(v, 0.0f), 1.0f);
        }

        // r channel: the only data anyone reads back.
        ((float4*)fr)[idx] = n;

        // Stage next step's exchange data (other parity slot; race-free).
        sInner[par ^ 1][half][c4] = n;
        if (lane == 0)  sEdge[par ^ 1][0][wid] = n.x;
        if (lane == 31) sEdge[par ^ 1][1][wid] = n.w;

        // Publish: bar orders r stores + smem staging, then release.
        __syncthreads();
        if (tid == 0) st_rel(flag_self, s + 1);

        // g/b: never read -> streaming stores, off the critical chain.
        float4* f4 = (float4*)fr;
        float4 t;
        t.x = n.x * 0.5f; t.y = n.y * 0.5f;
        t.z = n.z * 0.5f; t.w = n.w * 0.5f;
        __stcs(&f4[idx + (HW / 4)], t);
        t.x = 1.0f - n.x; t.y = 1.0f - n.y;
        t.z = 1.0f - n.z; t.w = 1.0f - n.w;
        __stcs(&f4[idx + 2 * (HW / 4)], t);

        u   = n;
        src = fr;
        fr += 3 * HW;
    }
}

extern "C" void kernel_launch(void* const* d_in, const int* in_sizes, int n_in,
                              void* d_out, int out_size) {
    const float* init = (const float*)d_in[0];
    float* out = (float*)d_out;
    const int n_frames = out_size / (3 * HW);

    reset_flags_kernel<<<NB / 256, 256>>>();
    physics_persistent_kernel<<<NB, 512>>>(init, out, n_frames);
}

// round 12
// speedup vs baseline: 1.0541x; 1.0541x over previous
#include <cuda_runtime.h>
#include <cstdint>

// 64 steps of diffusion-advection on a 1024x1024 periodic grid, emitting
// (T, 3, H, W) fp32 RGB, as ONE persistent kernel.  (R7 structure, with
// plain writeback stores instead of __stcs: L2 acts as a pulse-smoothing
// write reservoir so DRAM stays fed during the per-step sync chain.)
//
//  - r channel of frame s == u_{s+1} exactly (clipped); frames carry state.
//  - Per-row flags: producer block-bar + st.release.gpu; consumer
//    ld.acquire.gpu spin. One __syncthreads per step.
//  - Only the r store precedes the flag; g/b stores (2/3 of traffic, never
//    read) are issued after publish and drain via lazy L2 writeback.
//  - Warp-edge x-neighbors exchanged through parity-double-buffered smem.
//  - 1024 blocks x 256 threads, 1 row/block, u in registers; <=32 regs ->
//    8 blocks/SM, 1184 slots >= 1024 blocks (spin-safe co-residency).

#define HH 1024
#define WW 1024
#define HW (HH * WW)

#define DT     0.1f
#define ALPHA  0.05f
#define V_X    0.1f
// V_Y == 0 -> du_dy term vanishes.

#define NB 1024
#define FS 32                 // flag stride in ints (128 B)

__device__ int g_flags[NB * FS];

__global__ void reset_flags_kernel() {
    const int i = blockIdx.x * blockDim.x + threadIdx.x;   // 0..NB-1
    g_flags[i * FS] = 0;
}

__device__ __forceinline__ int ld_acq(const int* p) {
    int v;
    asm volatile("ld.acquire.gpu.global.b32 %0, [%1];"
                 : "=r"(v) : "l"(p) : "memory");
    return v;
}
__device__ __forceinline__ void st_rel(int* p, int v) {
    asm volatile("st.release.gpu.global.b32 [%0], %1;"
                 :: "l"(p), "r"(v) : "memory");
}

__global__ __launch_bounds__(256, 8)
void physics_persistent_kernel(const float* __restrict__ u_init,
                               float* __restrict__ frames,
                               int n_frames)
{
    // Edge exchange: [parity][0=first elem of warp][wid], [1=last][wid]
    __shared__ float sEdge[2][2][8];

    const int y    = blockIdx.x;          // owned row
    const int c4   = threadIdx.x;         // float4 column 0..255
    const int lane = c4 & 31;
    const int wid  = c4 >> 5;
    const int ym1  = (y - 1) & (HH - 1);
    const int yp1  = (y + 1) & (HH - 1);

    const int idx  = (y   << 8) + c4;     // float4 index within a channel
    const int idxu = (ym1 << 8) + c4;
    const int idxd = (yp1 << 8) + c4;

    int*       flag_self = &g_flags[y   * FS];
    const int* flag_up   = &g_flags[ym1 * FS];
    const int* flag_dn   = &g_flags[yp1 * FS];

    float4 u = ((const float4*)u_init)[idx];   // u_s for own row
    const float* src = u_init;                 // where u_s lives (r of s-1)
    float*       fr  = frames;                 // frame s base

    if (lane == 0)  sEdge[0][0][wid] = u.x;
    if (lane == 31) sEdge[0][1][wid] = u.w;
    __syncthreads();

    for (int s = 0; s < n_frames; ++s) {
        if (s > 0) {
            while (ld_acq(flag_up) < s) { }
            while (ld_acq(flag_dn) < s) { }
        }

        const float4* src4 = (const float4*)src;
        const float4 hu = __ldcg(&src4[idxu]);
        const float4 hd = __ldcg(&src4[idxd]);

        const int par = s & 1;
        const float lwS = sEdge[par][1][(wid - 1) & 7];
        const float rxS = sEdge[par][0][(wid + 1) & 7];

        float lw = __shfl_up_sync(0xffffffffu, u.w, 1);
        float rx = __shfl_down_sync(0xffffffffu, u.x, 1);
        if (lane == 0)  lw = lwS;
        if (lane == 31) rx = rxS;

        const float uc[4] = {u.x,  u.y,  u.z,  u.w};
        const float ul[4] = {lw,   u.x,  u.y,  u.z};
        const float ur[4] = {u.y,  u.z,  u.w,  rx};
        const float uu[4] = {hu.x, hu.y, hu.z, hu.w};
        const float ud[4] = {hd.x, hd.y, hd.z, hd.w};

        float4 n;
        float* np = &n.x;
        #pragma unroll
        for (int i = 0; i < 4; ++i) {
            const float lap = ul[i] + ur[i] + uu[i] + ud[i] - 4.0f * uc[i];
            float v = uc[i] + DT * (ALPHA * lap - V_X * (uc[i] - ul[i]));
            np[i] = fminf(fmaxf(v, 0.0f), 1.0f);
        }

        float4* f4 = (float4*)fr;
        f4[idx] = n;                       // r channel: the only re-read data

        // Stage next step's edges (other parity slot; race-free).
        if (lane == 0)  sEdge[par ^ 1][0][wid] = n.x;
        if (lane == 31) sEdge[par ^ 1][1][wid] = n.w;

        // Publish: barrier (all r stores + edge STS ordered) -> release.
        __syncthreads();
        if (c4 == 0) st_rel(flag_self, s + 1);

        // g/b: never read by anyone -> off the critical chain. Plain
        // writeback stores: L2 buffers the pulse and drains continuously.
        float4 t;
        t.x = n.x * 0.5f; t.y = n.y * 0.5f;
        t.z = n.z * 0.5f; t.w = n.w * 0.5f;
        f4[idx + (HW / 4)] = t;
        t.x = 1.0f - n.x; t.y = 1.0f - n.y;
        t.z = 1.0f - n.z; t.w = 1.0f - n.w;
        f4[idx + 2 * (HW / 4)] = t;

        u   = n;
        src = fr;          // r channel of frame s == u_{s+1}
        fr += 3 * HW;
    }
}

extern "C" void kernel_launch(void* const* d_in, const int* in_sizes, int n_in,
                              void* d_out, int out_size) {
    const float* init = (const float*)d_in[0];
    float* out = (float*)d_out;
    const int n_frames = out_size / (3 * HW);

    reset_flags_kernel<<<NB / 256, 256>>>();
    physics_persistent_kernel<<<NB, 256>>>(init, out, n_frames);
}